// round 1
// baseline (speedup 1.0000x reference)
#include <cuda_runtime.h>
#include <math.h>
#include <float.h>

// Problem constants (fixed shapes: B=32, S=128, V=8, T=66 -> 256 sequences)
#define TT    66
#define TP    68          // padded T (for float4 inner loop; pads held at 0)
#define SS    128
#define NSEQ  256
#define THREADS 160       // 5 warps; threads 0..131 are compute (2 seqs x 66 states)

__device__ float g_partial[NSEQ];

// Shared layout (floats):
//   emis  [2][SS*TT]            = 16896
//   ubuf  [2 seq][2 pingpong][TP] = 272
//   s_mx[2], s_L[2], s_gold[2]  = 6 (+2 pad)
//   gpart [256]
//   tags  [2][SS] (ints)
#define SMEM_FLOATS (2*SS*TT + 4*TP + 8 + 256)
#define SMEM_BYTES  (SMEM_FLOATS*4 + 2*SS*4)

__global__ void __launch_bounds__(THREADS, 1) crf_fwd_kernel(
    const float* __restrict__ score,        // [B,S,S,T]
    const float* __restrict__ trans,        // [T,T]
    const float* __restrict__ startT,       // [T]
    const float* __restrict__ endT,         // [T]
    const int*   __restrict__ v_label,      // [B,V] flattened = [256]
    const int*   __restrict__ role_label)   // [B,V,S] flattened = [256][128]
{
    extern __shared__ float sm[];
    float* emis   = sm;                       // [2][SS*TT]
    float* ubuf   = emis + 2*SS*TT;           // [2][2][TP]
    float* s_mx   = ubuf + 4*TP;              // [2]
    float* s_L    = s_mx + 2;                 // [2]
    float* s_gold = s_L + 2;                  // [2] (+2 pad floats after)
    float* gpart  = ubuf + 4*TP + 8;          // [256]
    int*   tagsh  = (int*)(gpart + 256);      // [2][SS]

    const int tid  = threadIdx.x;
    const int blk  = blockIdx.x;              // 0..127, seqs 2*blk, 2*blk+1
    const int lane = tid & 31;
    const int wid  = tid >> 5;

    // ---- Phase A: zero ping-pong buffers (pads stay 0 forever), load tiles ----
    for (int k = tid; k < 4*TP; k += THREADS) ubuf[k] = 0.f;

    #pragma unroll
    for (int l = 0; l < 2; l++) {
        int seq  = blk*2 + l;
        int b    = seq >> 3;                  // V = 8
        int vrow = v_label[seq];
        const float4* src = (const float4*)(score + ((size_t)(b*SS + vrow))*SS*TT);
        float4*       dst = (float4*)(emis + l*SS*TT);
        for (int k = tid; k < (SS*TT)/4; k += THREADS) dst[k] = src[k];
    }
    for (int k = tid; k < 2*SS; k += THREADS)
        tagsh[k] = role_label[blk*2*SS + k];

    // exp(transitions) column j into registers (shared across both seqs)
    const int  l      = (tid < TT) ? 0 : 1;
    const int  j      = tid - l*TT;
    const bool active = (tid < 2*TT);
    float e[TP];
    if (active) {
        #pragma unroll
        for (int i = 0; i < TT; i++) e[i] = __expf(trans[i*TT + j]);
        e[66] = 0.f; e[67] = 0.f;
    }
    __syncthreads();

    // ---- Phase B: gold-path partials + u init (t = 0) ----
    for (int idx = tid; idx < 2*SS; idx += THREADS) {
        int ls = idx >> 7;
        int s  = idx & (SS-1);
        int tg = tagsh[ls*SS + s];
        float g = emis[ls*SS*TT + s*TT + tg];
        if (s < SS-1) g += trans[tg*TT + tagsh[ls*SS + s + 1]];
        else          g += endT[tg];
        if (s == 0)   g += startT[tg];
        gpart[idx] = g;
    }
    if (active) {
        // raw u0 = exp(start + emit_0); invariant: alpha_t[j] = log(u[j]*inv) + L
        ubuf[(l*2 + 0)*TP + j] = __expf(startT[j] + emis[l*SS*TT + j]);
    }
    __syncthreads();

    // ---- Phase C: init reductions (max of u0 per seq; gold sum per seq) ----
    if (wid < 2) {
        const float* ub = ubuf + (wid*2)*TP;
        float m = fmaxf(ub[lane], ub[lane + 32]);
        if (lane < 4) m = fmaxf(m, ub[lane + 64]);   // 64..67 incl. zero pads
        #pragma unroll
        for (int o = 16; o; o >>= 1) m = fmaxf(m, __shfl_xor_sync(0xffffffffu, m, o));
        if (lane == 0) { s_mx[wid] = m; s_L[wid] = __logf(m); }
    } else if (wid < 4) {
        int ls = wid - 2;
        const float* gp = gpart + ls*SS;
        float g = (gp[lane] + gp[lane + 32]) + (gp[lane + 64] + gp[lane + 96]);
        #pragma unroll
        for (int o = 16; o; o >>= 1) g += __shfl_xor_sync(0xffffffffu, g, o);
        if (lane == 0) s_gold[ls] = g;
    }
    __syncthreads();

    // ---- Main scan: 127 serial steps of scaled 66x66 GEMV ----
    int cur = 0;
    for (int t = 1; t < SS; t++) {
        const int nxt = cur ^ 1;
        if (active) {
            const float* u = ubuf + (l*2 + cur)*TP;
            float d0 = 0.f, d1 = 0.f, d2 = 0.f, d3 = 0.f;
            #pragma unroll
            for (int g4 = 0; g4 < TP/4; g4++) {
                float4 uu = ((const float4*)u)[g4];
                d0 = fmaf(uu.x, e[4*g4 + 0], d0);
                d1 = fmaf(uu.y, e[4*g4 + 1], d1);
                d2 = fmaf(uu.z, e[4*g4 + 2], d2);
                d3 = fmaf(uu.w, e[4*g4 + 3], d3);
            }
            float dot  = (d0 + d1) + (d2 + d3);
            float invv = 1.0f / s_mx[l];   // pending scale from previous step
            float r = dot * invv * __expf(emis[l*SS*TT + t*TT + j]);
            ubuf[(l*2 + nxt)*TP + j] = r;
        }
        __syncthreads();
        if (wid < 2) {
            const float* ub = ubuf + (wid*2 + nxt)*TP;
            float m = fmaxf(ub[lane], ub[lane + 32]);
            if (lane < 4) m = fmaxf(m, ub[lane + 64]);
            #pragma unroll
            for (int o = 16; o; o >>= 1) m = fmaxf(m, __shfl_xor_sync(0xffffffffu, m, o));
            if (lane == 0) { s_mx[wid] = m; s_L[wid] += __logf(m); }
        }
        __syncthreads();
        cur = nxt;
    }

    // ---- Epilogue: logZ = log(inv * sum_j u_j * exp(end_j)) + L ----
    const int other = cur ^ 1;
    if (active) {
        float w = ubuf[(l*2 + cur)*TP + j] * __expf(endT[j]);
        ubuf[(l*2 + other)*TP + j] = w;    // pads in 'other' are still 0
    }
    __syncthreads();
    if (wid < 2) {
        const float* ub = ubuf + (wid*2 + other)*TP;
        float sv = ub[lane] + ub[lane + 32];
        if (lane < 4) sv += ub[lane + 64];
        #pragma unroll
        for (int o = 16; o; o >>= 1) sv += __shfl_xor_sync(0xffffffffu, sv, o);
        if (lane == 0) {
            float logZ = __logf(sv / s_mx[wid]) + s_L[wid];
            g_partial[blk*2 + wid] = logZ - s_gold[wid];
        }
    }
}

__global__ void crf_reduce_kernel(float* __restrict__ out) {
    __shared__ float sh[NSEQ];
    int t = threadIdx.x;
    sh[t] = g_partial[t];
    __syncthreads();
    #pragma unroll
    for (int s = NSEQ/2; s > 0; s >>= 1) {
        if (t < s) sh[t] += sh[t + s];
        __syncthreads();
    }
    if (t == 0) out[0] = sh[0] * (1.0f / (float)NSEQ);
}

extern "C" void kernel_launch(void* const* d_in, const int* in_sizes, int n_in,
                              void* d_out, int out_size) {
    const float* score      = (const float*)d_in[0];
    const float* trans      = (const float*)d_in[1];
    const float* startT     = (const float*)d_in[2];
    const float* endT       = (const float*)d_in[3];
    const int*   v_label    = (const int*)d_in[4];
    const int*   role_label = (const int*)d_in[5];
    float* out = (float*)d_out;

    // idempotent; > 48KB dynamic smem requires opt-in
    cudaFuncSetAttribute(crf_fwd_kernel,
                         cudaFuncAttributeMaxDynamicSharedMemorySize, SMEM_BYTES);

    crf_fwd_kernel<<<NSEQ/2, THREADS, SMEM_BYTES>>>(
        score, trans, startT, endT, v_label, role_label);
    crf_reduce_kernel<<<1, NSEQ>>>(out);
}

// round 2
// speedup vs baseline: 1.5099x; 1.5099x over previous
#include <cuda_runtime.h>
#include <math.h>

// Fixed shapes: B=32, S=128, V=8, T=66 -> 256 independent sequences
#define TT    66
#define TP    68           // padded T (pads held at 0)
#define SS    128
#define NSEQ  256
#define NBLK  (NSEQ/2)
#define THREADS 160        // 5 warps; threads 0..131 = 2 seqs x 66 states

__device__ float        g_partial[NSEQ];
__device__ unsigned int g_count = 0;   // self-resetting completion counter

// ---- packed f32x2 helpers (Blackwell FFMA2 path) ----
__device__ __forceinline__ unsigned long long pk2(float lo, float hi) {
    unsigned long long r;
    asm("mov.b64 %0, {%1, %2};" : "=l"(r) : "f"(lo), "f"(hi));
    return r;
}
__device__ __forceinline__ void fma2(unsigned long long& d,
                                     unsigned long long a, unsigned long long b) {
    asm("fma.rn.f32x2 %0, %1, %2, %0;" : "+l"(d) : "l"(a), "l"(b));
}
__device__ __forceinline__ void add2(unsigned long long& d,
                                     unsigned long long a, unsigned long long b) {
    asm("add.rn.f32x2 %0, %1, %2;" : "=l"(d) : "l"(a), "l"(b));
}
__device__ __forceinline__ float2 upk2(unsigned long long v) {
    float lo, hi;
    asm("mov.b64 {%0, %1}, %2;" : "=f"(lo), "=f"(hi) : "l"(v));
    return make_float2(lo, hi);
}

// Shared floats: emisExp[2][SS*TT] + ubuf[2][2][TP] + s_inv[2] + s_L[2]
//                + s_gold[2] + s_out[2] + gpart[256] + flag
#define SMEM_FLOATS (2*SS*TT + 4*TP + 8 + 256 + 4)
#define SMEM_BYTES  (SMEM_FLOATS*4)

__global__ void __launch_bounds__(THREADS, 1) crf_fused_kernel(
    const float* __restrict__ score,        // [B,S,S,T]
    const float* __restrict__ trans,        // [T,T]
    const float* __restrict__ startT,       // [T]
    const float* __restrict__ endT,         // [T]
    const int*   __restrict__ v_label,      // [B*V]
    const int*   __restrict__ role_label,   // [B*V][S]
    float*       __restrict__ out)
{
    extern __shared__ float sm[];
    float* emis   = sm;                 // [2][SS*TT]   exp(emissions)
    float* ubuf   = emis + 2*SS*TT;     // [2 seq][2 pp][TP]
    float* s_inv  = ubuf + 4*TP;        // [2] pending 1/max scale
    float* s_L    = s_inv + 2;          // [2] accumulated log scale
    float* s_gold = s_L + 2;            // [2]
    float* s_out  = s_gold + 2;         // [2]
    float* gpart  = s_out + 2;          // [256]
    int*   s_flag = (int*)(gpart + 256);

    const int tid  = threadIdx.x;
    const int blk  = blockIdx.x;        // seqs 2*blk, 2*blk+1
    const int lane = tid & 31;
    const int wid  = tid >> 5;

    // ---- Phase A: zero ping-pong pads, load emissions fused with exp ----
    for (int k = tid; k < 4*TP; k += THREADS) ubuf[k] = 0.f;

    #pragma unroll
    for (int l2 = 0; l2 < 2; l2++) {
        int seq = blk*2 + l2;
        int b   = seq >> 3;                         // V = 8
        int vr  = __ldg(&v_label[seq]);
        const float4* src = (const float4*)(score + ((size_t)(b*SS + vr))*SS*TT);
        float4*       dst = (float4*)(emis + l2*SS*TT);
        for (int k = tid; k < (SS*TT)/4; k += THREADS) {
            float4 v = __ldg(&src[k]);
            v.x = __expf(v.x); v.y = __expf(v.y);
            v.z = __expf(v.z); v.w = __expf(v.w);
            dst[k] = v;
        }
    }

    // ---- gold-path partials straight from global (raw values) ----
    for (int idx = tid; idx < 2*SS; idx += THREADS) {
        int ls  = idx >> 7;
        int s   = idx & (SS-1);
        int seq = blk*2 + ls;
        int b   = seq >> 3;
        int vr  = __ldg(&v_label[seq]);
        const float* row = score + ((size_t)(b*SS + vr))*SS*TT;
        int tg = __ldg(&role_label[seq*SS + s]);
        float g = __ldg(&row[s*TT + tg]);
        if (s < SS-1) {
            int tn = __ldg(&role_label[seq*SS + s + 1]);
            g += __ldg(&trans[tg*TT + tn]);
        } else {
            g += __ldg(&endT[tg]);
        }
        if (s == 0) g += __ldg(&startT[tg]);
        gpart[idx] = g;
    }

    // ---- exp(transitions) column j, packed in register pairs over i ----
    const int  l      = (tid < TT) ? 0 : 1;
    const int  j      = tid - l*TT;
    const bool active = (tid < 2*TT);
    unsigned long long e2[TP/2];
    float eEnd = 0.f, eStart = 0.f;
    if (active) {
        #pragma unroll
        for (int k = 0; k < 33; k++) {
            float lo = __expf(__ldg(&trans[(2*k  )*TT + j]));
            float hi = __expf(__ldg(&trans[(2*k+1)*TT + j]));
            e2[k] = pk2(lo, hi);
        }
        e2[33] = 0ULL;                       // i = 66,67 pads
        eEnd   = __expf(__ldg(&endT[j]));
        eStart = __expf(__ldg(&startT[j]));
    }
    __syncthreads();

    // ---- u0 = exp(start_j) * expEmit[0][j] ----
    if (active) ubuf[(l*2 + 0)*TP + j] = eStart * emis[l*SS*TT + j];
    __syncthreads();

    // ---- init reductions: max(u0) per seq (warps 0,1), gold sum (warps 2,3) ----
    if (wid < 2) {
        const float* ub = ubuf + (wid*2)*TP;
        float m = fmaxf(ub[lane], ub[lane + 32]);
        if (lane < 4) m = fmaxf(m, ub[lane + 64]);   // pads are 0, u > 0
        #pragma unroll
        for (int o = 16; o; o >>= 1) m = fmaxf(m, __shfl_xor_sync(0xffffffffu, m, o));
        if (lane == 0) { s_inv[wid] = 1.0f/m; s_L[wid] = __logf(m); }
    } else if (wid < 4) {
        int ls = wid - 2;
        const float* gp = gpart + ls*SS;
        float g = (gp[lane] + gp[lane + 32]) + (gp[lane + 64] + gp[lane + 96]);
        #pragma unroll
        for (int o = 16; o; o >>= 1) g += __shfl_xor_sync(0xffffffffu, g, o);
        if (lane == 0) s_gold[ls] = g;
    }
    __syncthreads();

    // ---- main scan: 127 scaled-GEMV steps, renorm every 8 steps ----
    const float* uE = emis + l*SS*TT;

    // one step: u_new[j] = (sum_i u_i * E_ij) * sc * expEmit[t][j]
    auto dostep = [&](int t, int cur, float sc) {
        float em = uE[t*TT + j];                      // issue LDS early
        const ulonglong2* up = (const ulonglong2*)(ubuf + (l*2 + cur)*TP);
        unsigned long long d0 = 0ULL, d1 = 0ULL, d2 = 0ULL, d3 = 0ULL;
        #pragma unroll
        for (int k = 0; k < 17; k++) {
            ulonglong2 uu = up[k];
            if (k & 1) { fma2(d2, uu.x, e2[2*k]); fma2(d3, uu.y, e2[2*k+1]); }
            else       { fma2(d0, uu.x, e2[2*k]); fma2(d1, uu.y, e2[2*k+1]); }
        }
        add2(d0, d0, d2); add2(d1, d1, d3); add2(d0, d0, d1);
        float2 f = upk2(d0);
        ubuf[(l*2 + (cur^1))*TP + j] = (f.x + f.y) * sc * em;
    };

    int cur = 0;
    int t   = 1;
    while (t < SS) {
        // first step of group consumes the pending scale
        if (active) dostep(t, cur, s_inv[l]);
        __syncthreads();
        cur ^= 1; t++;
        int lim = t + 7; if (lim > SS) lim = SS;
        for (; t < lim; t++) {
            if (active) dostep(t, cur, 1.0f);
            __syncthreads();
            cur ^= 1;
        }
        if (t < SS) {   // renorm: m = max(u); pend 1/m; L += log m
            if (wid < 2) {
                const float* ub = ubuf + (wid*2 + cur)*TP;
                float m = fmaxf(ub[lane], ub[lane + 32]);
                if (lane < 4) m = fmaxf(m, ub[lane + 64]);
                #pragma unroll
                for (int o = 16; o; o >>= 1) m = fmaxf(m, __shfl_xor_sync(0xffffffffu, m, o));
                if (lane == 0) { s_inv[wid] = 1.0f/m; s_L[wid] += __logf(m); }
            }
            __syncthreads();
        }
    }

    // ---- epilogue: logZ = log(sum_j u_j * exp(end_j)) + L ----
    const int oth = cur ^ 1;
    if (active) ubuf[(l*2 + oth)*TP + j] = ubuf[(l*2 + cur)*TP + j] * eEnd;
    __syncthreads();
    if (wid < 2) {
        const float* ub = ubuf + (wid*2 + oth)*TP;
        float sv = ub[lane] + ub[lane + 32];
        if (lane < 4) sv += ub[lane + 64];
        #pragma unroll
        for (int o = 16; o; o >>= 1) sv += __shfl_xor_sync(0xffffffffu, sv, o);
        if (lane == 0) s_out[wid] = __logf(sv) + s_L[wid] - s_gold[wid];
    }
    __syncthreads();

    // ---- fused final reduction: last block to finish sums all partials ----
    if (tid == 0) {
        __stcg(&g_partial[blk*2 + 0], s_out[0]);
        __stcg(&g_partial[blk*2 + 1], s_out[1]);
        __threadfence();
        unsigned c = atomicAdd(&g_count, 1u);
        *s_flag = (c == NBLK - 1) ? 1 : 0;
    }
    __syncthreads();
    if (*s_flag) {
        float v = __ldcg(&g_partial[tid]);
        if (tid < NSEQ - THREADS) v += __ldcg(&g_partial[tid + THREADS]);
        #pragma unroll
        for (int o = 16; o; o >>= 1) v += __shfl_xor_sync(0xffffffffu, v, o);
        if (lane == 0) gpart[wid] = v;           // reuse smem scratch
        __syncthreads();
        if (tid == 0) {
            float tot = ((gpart[0] + gpart[1]) + (gpart[2] + gpart[3])) + gpart[4];
            out[0] = tot * (1.0f / (float)NSEQ);
            g_count = 0;                          // reset for next graph replay
        }
    }
}

extern "C" void kernel_launch(void* const* d_in, const int* in_sizes, int n_in,
                              void* d_out, int out_size) {
    const float* score      = (const float*)d_in[0];
    const float* trans      = (const float*)d_in[1];
    const float* startT     = (const float*)d_in[2];
    const float* endT       = (const float*)d_in[3];
    const int*   v_label    = (const int*)d_in[4];
    const int*   role_label = (const int*)d_in[5];
    float* out = (float*)d_out;

    cudaFuncSetAttribute(crf_fused_kernel,
                         cudaFuncAttributeMaxDynamicSharedMemorySize, SMEM_BYTES);

    crf_fused_kernel<<<NBLK, THREADS, SMEM_BYTES>>>(
        score, trans, startT, endT, v_label, role_label, out);
}

// round 3
// speedup vs baseline: 1.7568x; 1.1635x over previous
#include <cuda_runtime.h>
#include <math.h>

// Fixed shapes: B=32, S=128, V=8, T=66 -> 256 independent sequences.
// One warp per sequence; 4 warps (4 seqs) per block; 64 blocks.
#define TT   66
#define SS   128
#define NSEQ 256
#define WPB  4
#define NBLK (NSEQ/WPB)

typedef unsigned long long ull;

__device__ float        g_partial[NSEQ];
__device__ unsigned int g_count = 0;   // self-resetting completion counter

static __device__ __forceinline__ ull pk2(float lo, float hi) {
    ull r; asm("mov.b64 %0, {%1,%2};" : "=l"(r) : "f"(lo), "f"(hi)); return r;
}
static __device__ __forceinline__ void fma2(ull& d, ull a, ull b) {
    asm("fma.rn.f32x2 %0, %1, %2, %0;" : "+l"(d) : "l"(a), "l"(b));
}
static __device__ __forceinline__ void add2(ull& d, ull a, ull b) {
    asm("add.rn.f32x2 %0, %1, %2;" : "=l"(d) : "l"(a), "l"(b));
}
static __device__ __forceinline__ float2 upk2(ull v) {
    float lo, hi; asm("mov.b64 {%0,%1}, %2;" : "=f"(lo), "=f"(hi) : "l"(v));
    return make_float2(lo, hi);
}

__global__ void __launch_bounds__(32*WPB, 1) crf_kernel(
    const float* __restrict__ score,       // [B,S,S,T]
    const float* __restrict__ trans,       // [T,T]
    const float* __restrict__ startT,      // [T]
    const float* __restrict__ endT,        // [T]
    const int*   __restrict__ v_label,     // [B*V]
    const int*   __restrict__ role_label,  // [B*V][S]
    float*       __restrict__ out)
{
    // duplicated-u ping-pong: float4 m = (u[2m],u[2m],u[2m+1],u[2m+1]); slot 32 = states 64,65
    __shared__ __align__(16) float4 bufA[WPB][33];
    __shared__ __align__(16) float4 bufB[WPB][33];
    __shared__ float s_red[WPB];
    __shared__ int   s_flag;

    const int tid  = threadIdx.x;
    const int lane = tid & 31;
    const int w    = tid >> 5;
    const int seq  = blockIdx.x * WPB + w;
    const int b    = seq >> 3;                       // V = 8
    const int vr   = __ldg(&v_label[seq]);
    const float* erow = score + ((size_t)(b*SS + vr))*SS*TT;   // raw emissions [S][T]

    float4* A = bufA[w];
    float4* B = bufB[w];

    // ---- emission prefetch rings for t = 1..4 (main pair + cols 64,65) ----
    float2 emA[4], emX[4];
    #pragma unroll
    for (int r = 0; r < 4; r++) {
        emA[r] = __ldg((const float2*)(erow + (1+r)*TT) + lane);
        emX[r] = __ldg((const float2*)(erow + (1+r)*TT + 64));
    }

    // ---- gold-path score (4 positions per lane, butterfly sum) ----
    float gold = 0.f;
    #pragma unroll
    for (int p = 0; p < 4; p++) {
        int s  = lane + 32*p;
        int tg = __ldg(&role_label[seq*SS + s]);
        float g = __ldg(&erow[s*TT + tg]);
        if (s < SS-1) {
            int tn = __ldg(&role_label[seq*SS + s + 1]);
            g += __ldg(&trans[tg*TT + tn]);
        } else {
            g += __ldg(&endT[tg]);
        }
        if (s == 0) g += __ldg(&startT[tg]);
        gold += g;
    }
    #pragma unroll
    for (int o = 16; o; o >>= 1) gold += __shfl_xor_sync(~0u, gold, o);

    // ---- exp(E) columns (2k, 2k+1) into registers, packed over rows ----
    ull e2[TT];
    #pragma unroll
    for (int i = 0; i < TT; i++) {
        float2 tv = __ldg((const float2*)(trans + i*TT) + lane);
        e2[i] = pk2(__expf(tv.x), __expf(tv.y));
    }
    // extra output pair (cols 64,65): my rows 2k,2k+1; rows 64,65 on lanes 0,1
    float2 x0 = __ldg((const float2*)(trans + (2*lane  )*TT + 64));
    float2 x1 = __ldg((const float2*)(trans + (2*lane+1)*TT + 64));
    ull ex0 = pk2(__expf(x0.x), __expf(x0.y));
    ull ex1 = pk2(__expf(x1.x), __expf(x1.y));
    ull ex2 = 0;
    if (lane < 2) {
        float2 x2 = __ldg((const float2*)(trans + (64+lane)*TT + 64));
        ex2 = pk2(__expf(x2.x), __expf(x2.y));
    }
    float2 eEnd  = __ldg((const float2*)endT + lane);
    float2 eEndX = __ldg((const float2*)(endT + 64));

    // ---- u0 = exp(start + emit[0]) ----
    float2 st   = __ldg((const float2*)startT + lane);
    float2 e0   = __ldg((const float2*)erow + lane);
    float2 st64 = __ldg((const float2*)(startT + 64));
    float2 e064 = __ldg((const float2*)(erow + 64));
    float rx  = __expf(st.x   + e0.x);
    float ry  = __expf(st.y   + e0.y);
    float r64 = __expf(st64.x + e064.x);
    float r65 = __expf(st64.y + e064.y);

    A[lane] = make_float4(rx, rx, ry, ry);
    if (lane == 0) A[32] = make_float4(r64, r64, r65, r65);

    // init renorm (pending scale, applied on next step's result)
    float m0 = fmaxf(fmaxf(rx, ry), fmaxf(r64, r65));
    #pragma unroll
    for (int o = 16; o; o >>= 1) m0 = fmaxf(m0, __shfl_xor_sync(~0u, m0, o));
    float sc = __fdividef(1.0f, m0);
    float L  = __logf(m0);
    __syncwarp();

    // ---- one scan step: u' = (E^T u) * scale * exp(emit_t), warp-synchronous ----
    auto STEP = [&](int t, int slot, const float4* cur, float4* nxt, float scale) {
        float2 ea  = emA[slot];
        float2 exm = emX[slot];
        if (t + 4 < SS) {                       // refill ring slot for t+4
            emA[slot] = __ldg((const float2*)(erow + (t+4)*TT) + lane);
            emX[slot] = __ldg((const float2*)(erow + (t+4)*TT + 64));
        }
        const ulonglong2* up = (const ulonglong2*)cur;
        ull d0 = 0, d1 = 0, d2 = 0, d3 = 0;
        #pragma unroll
        for (int mm = 0; mm < 33; mm++) {
            ulonglong2 uu = up[mm];             // broadcast: ((u_2m,u_2m),(u_2m+1,u_2m+1))
            if (mm & 1) { fma2(d2, uu.x, e2[2*mm]); fma2(d3, uu.y, e2[2*mm+1]); }
            else        { fma2(d0, uu.x, e2[2*mm]); fma2(d1, uu.y, e2[2*mm+1]); }
        }
        // cooperative extra pair (cols 64,65): partial over my rows, then butterfly
        ulonglong2 mu = up[lane];
        ull dx = 0;
        fma2(dx, mu.x, ex0);
        fma2(dx, mu.y, ex1);
        if (lane < 2) {
            ull uvw = ((const ull*)cur)[64 + lane];
            fma2(dx, uvw, ex2);
        }
        float2 fp = upk2(dx);
        float fx = fp.x, fy = fp.y;
        #pragma unroll
        for (int o = 16; o; o >>= 1) {
            fx += __shfl_xor_sync(~0u, fx, o);
            fy += __shfl_xor_sync(~0u, fy, o);
        }
        add2(d0, d0, d2); add2(d1, d1, d3); add2(d0, d0, d1);
        float2 f = upk2(d0);
        rx  = f.x * (scale * __expf(ea.x));
        ry  = f.y * (scale * __expf(ea.y));
        r64 = fx  * (scale * __expf(exm.x));
        r65 = fy  * (scale * __expf(exm.y));
        nxt[lane] = make_float4(rx, rx, ry, ry);
        if (lane == 0) nxt[32] = make_float4(r64, r64, r65, r65);
        __syncwarp();
    };

    // ---- main scan: 15 groups of 8 steps + 7-step tail; renorm at group ends ----
    int t = 1;
    for (int g = 0; g < 15; g++) {
        #pragma unroll
        for (int q = 0; q < 8; q++) {
            const int slot = (1 + q) & 3;       // == t & 3 (t = 8g+1+q)
            if (q & 1) STEP(t, slot, B, A, 1.0f);
            else       STEP(t, slot, A, B, (q == 0) ? sc : 1.0f);
            t++;
        }
        float mg = fmaxf(fmaxf(rx, ry), fmaxf(r64, r65));
        #pragma unroll
        for (int o = 16; o; o >>= 1) mg = fmaxf(mg, __shfl_xor_sync(~0u, mg, o));
        sc = __fdividef(1.0f, mg);
        L += __logf(mg);
    }
    #pragma unroll
    for (int q = 0; q < 7; q++) {               // t = 121..127
        const int slot = (1 + q) & 3;
        if (q & 1) STEP(t, slot, B, A, 1.0f);
        else       STEP(t, slot, A, B, (q == 0) ? sc : 1.0f);
        t++;
    }

    // ---- epilogue: logZ = log(sum_j u_j * exp(end_j)) + L ----
    float wsum = rx * __expf(eEnd.x) + ry * __expf(eEnd.y);
    if (lane == 0) wsum += r64 * __expf(eEndX.x) + r65 * __expf(eEndX.y);
    #pragma unroll
    for (int o = 16; o; o >>= 1) wsum += __shfl_xor_sync(~0u, wsum, o);
    if (lane == 0) {
        __stcg(&g_partial[seq], __logf(wsum) + L - gold);
        __threadfence();
    }

    // ---- fused final reduction: last block to finish sums all 256 partials ----
    __syncthreads();
    if (tid == 0) {
        unsigned c = atomicAdd(&g_count, 1u);
        s_flag = (c == NBLK - 1) ? 1 : 0;
    }
    __syncthreads();
    if (s_flag) {
        float v = __ldcg(&g_partial[tid]) + __ldcg(&g_partial[tid + 128]);
        #pragma unroll
        for (int o = 16; o; o >>= 1) v += __shfl_xor_sync(~0u, v, o);
        if (lane == 0) s_red[w] = v;
        __syncthreads();
        if (tid == 0) {
            out[0] = ((s_red[0] + s_red[1]) + (s_red[2] + s_red[3])) * (1.0f / (float)NSEQ);
            g_count = 0;                        // reset for next graph replay
        }
    }
}

extern "C" void kernel_launch(void* const* d_in, const int* in_sizes, int n_in,
                              void* d_out, int out_size) {
    const float* score      = (const float*)d_in[0];
    const float* trans      = (const float*)d_in[1];
    const float* startT     = (const float*)d_in[2];
    const float* endT       = (const float*)d_in[3];
    const int*   v_label    = (const int*)d_in[4];
    const int*   role_label = (const int*)d_in[5];
    float* out = (float*)d_out;

    crf_kernel<<<NBLK, 32*WPB>>>(score, trans, startT, endT, v_label, role_label, out);
}

// round 4
// speedup vs baseline: 1.9599x; 1.1156x over previous
#include <cuda_runtime.h>
#include <math.h>

// Fixed shapes: B=32, S=128, V=8, T=66 -> 256 independent sequences.
// One block (64 threads = 2 warps) per sequence. Warp w owns columns 32w+lane.
#define TT   66
#define SS   128
#define NSEQ 256

typedef unsigned long long ull;

__device__ float        g_partial[NSEQ];
__device__ unsigned int g_count = 0;

static __device__ __forceinline__ ull pk2(float lo, float hi) {
    ull r; asm("mov.b64 %0, {%1,%2};" : "=l"(r) : "f"(lo), "f"(hi)); return r;
}
static __device__ __forceinline__ void fma2(ull& d, ull a, ull b) {
    asm("fma.rn.f32x2 %0, %1, %2, %0;" : "+l"(d) : "l"(a), "l"(b));
}
static __device__ __forceinline__ void add2(ull& d, ull a, ull b) {
    asm("add.rn.f32x2 %0, %1, %2;" : "=l"(d) : "l"(a), "l"(b));
}
static __device__ __forceinline__ float2 upk2(ull v) {
    float lo, hi; asm("mov.b64 {%0,%1}, %2;" : "=f"(lo), "=f"(hi) : "l"(v));
    return make_float2(lo, hi);
}

__global__ void __launch_bounds__(64, 2) crf_kernel(
    const float* __restrict__ score,       // [B,S,S,T]
    const float* __restrict__ trans,       // [T,T]
    const float* __restrict__ startT,      // [T]
    const float* __restrict__ endT,        // [T]
    const int*   __restrict__ v_label,     // [B*V]
    const int*   __restrict__ role_label,  // [B*V][S]
    float*       __restrict__ out)
{
    __shared__ __align__(16) float u[2][72];   // ping-pong u vector, pads 66..71 = 0
    __shared__ float smax[2];                   // per-warp renorm max
    __shared__ float sgold[2], swsum[2], sred[2];
    __shared__ int   sflag;

    const int tid  = threadIdx.x;
    const int lane = tid & 31;
    const int w    = tid >> 5;
    const int seq  = blockIdx.x;
    const int b    = seq >> 3;                 // V = 8
    const int vr   = __ldg(&v_label[seq]);
    const float* erow = score + ((size_t)(b*SS + vr))*SS*TT;   // [S][T] emissions

    const int c  = 32*w + lane;                // my output column
    const int xc = 64 + w;                     // warp's extra column (64 or 65)
    const int g  = lane & 3;                   // redundancy group

    // zero pads of both u buffers
    if (tid < 6)  u[0][66 + tid] = 0.f;
    else if (tid < 12) u[1][66 + tid - 6] = 0.f;

    // emission prefetch rings for t = 1..4
    float emr[4], emx[4];
    #pragma unroll
    for (int r4 = 0; r4 < 4; r4++) {
        emr[r4] = __ldg(erow + (1+r4)*TT + c);
        emx[r4] = __ldg(erow + (1+r4)*TT + xc);
    }

    // ---- gold path: positions 2*tid, 2*tid+1 ----
    float gold = 0.f;
    #pragma unroll
    for (int p = 0; p < 2; p++) {
        int s  = 2*tid + p;
        int tg = __ldg(&role_label[seq*SS + s]);
        float gg = __ldg(&erow[s*TT + tg]);
        if (s < SS-1) gg += __ldg(&trans[tg*TT + __ldg(&role_label[seq*SS + s + 1])]);
        else          gg += __ldg(&endT[tg]);
        if (s == 0)   gg += __ldg(&startT[tg]);
        gold += gg;
    }
    #pragma unroll
    for (int o = 16; o; o >>= 1) gold += __shfl_xor_sync(~0u, gold, o);
    if (lane == 0) sgold[w] = gold;

    // ---- exp(E) for my column: 34 row-pairs (rows 66,67 pad = 0) ----
    ull e2[34];
    #pragma unroll
    for (int m = 0; m < 33; m++)
        e2[m] = pk2(__expf(__ldg(&trans[(2*m  )*TT + c])),
                    __expf(__ldg(&trans[(2*m+1)*TT + c])));
    e2[33] = 0ULL;

    // ---- exp(E) for extra column, my group's 8 row-pairs + pair (32+g) ----
    ull ex[9];
    #pragma unroll
    for (int q = 0; q < 8; q++) {
        int rr = 16*g + 2*q;
        ex[q] = pk2(__expf(__ldg(&trans[rr*TT + xc])),
                    __expf(__ldg(&trans[(rr+1)*TT + xc])));
    }
    ex[8] = (g == 0) ? pk2(__expf(__ldg(&trans[64*TT + xc])),
                           __expf(__ldg(&trans[65*TT + xc]))) : 0ULL;

    const float eEnd  = __expf(__ldg(&endT[c]));
    const float eEndX = __expf(__ldg(&endT[xc]));

    // ---- u0 = exp(start + emit[0]); init "renorm" pending ----
    float r  = __expf(__ldg(&startT[c])  + __ldg(&erow[c]));
    float rx = __expf(__ldg(&startT[xc]) + __ldg(&erow[xc]));
    u[0][c] = r;
    if (lane == 0) u[0][xc] = rx;
    {
        float m = fmaxf(r, rx);
        #pragma unroll
        for (int o = 16; o; o >>= 1) m = fmaxf(m, __shfl_xor_sync(~0u, m, o));
        if (lane == 0) smax[w] = m;
    }
    __syncthreads();

    float L = 0.f;

    // ---- one scan step ----
    auto STEP = [&](const float* pref, int slot, int cur, float scale, bool renorm) {
        float em  = emr[slot];
        float emX = emx[slot];
        if (pref) {                             // refill ring (t+4)
            emr[slot] = __ldg(pref + c);
            emx[slot] = __ldg(pref + xc);
        }
        const float* uc = u[cur];
        // extra column partial (group-redundant), started early
        ull x0 = 0, x1 = 0;
        {
            const ulonglong2* upx = (const ulonglong2*)(uc + 16*g);
            ulonglong2 a0 = upx[0], a1 = upx[1], a2 = upx[2], a3 = upx[3];
            ull a4 = *(const ull*)(uc + 64 + 2*g);
            fma2(x0, a0.x, ex[0]); fma2(x1, a0.y, ex[1]);
            fma2(x0, a1.x, ex[2]); fma2(x1, a1.y, ex[3]);
            fma2(x0, a2.x, ex[4]); fma2(x1, a2.y, ex[5]);
            fma2(x0, a3.x, ex[6]); fma2(x1, a3.y, ex[7]);
            fma2(x0, a4,   ex[8]);
        }
        // main: my column over all 34 row-pairs (broadcast loads)
        const ulonglong2* up = (const ulonglong2*)uc;
        ull d0 = 0, d1 = 0, d2 = 0, d3 = 0;
        #pragma unroll
        for (int i = 0; i < 17; i++) {
            ulonglong2 v = up[i];
            if (i & 1) { fma2(d2, v.x, e2[2*i]); fma2(d3, v.y, e2[2*i+1]); }
            else       { fma2(d0, v.x, e2[2*i]); fma2(d1, v.y, e2[2*i+1]); }
        }
        // finish extra column: 2-level reduce within 4-lane clusters
        add2(x0, x0, x1);
        float2 xf = upk2(x0);
        float fx = xf.x + xf.y;
        fx += __shfl_xor_sync(~0u, fx, 1);
        fx += __shfl_xor_sync(~0u, fx, 2);
        // finish main column
        add2(d0, d0, d2); add2(d1, d1, d3); add2(d0, d0, d1);
        float2 f = upk2(d0);
        r  = (f.x + f.y) * (scale * __expf(em));
        rx = fx          * (scale * __expf(emX));
        float* un = u[cur ^ 1];
        un[c] = r;
        if (lane == 0) un[xc] = rx;
        if (renorm) {                           // subset max (16 lanes) = range control
            float mm = fmaxf(r, rx);
            mm = fmaxf(mm, __shfl_xor_sync(~0u, mm, 1));
            mm = fmaxf(mm, __shfl_xor_sync(~0u, mm, 2));
            mm = fmaxf(mm, __shfl_xor_sync(~0u, mm, 4));
            mm = fmaxf(mm, __shfl_xor_sync(~0u, mm, 8));
            if (lane == 0) smax[w] = mm;
        }
        __syncthreads();
    };

    // ---- main scan: 15 groups of 8 + tail of 7; renorm at group ends ----
    const float* pe = erow + 5*TT;   // refill source for t=1 is row t+4=5
    for (int grp = 0; grp < 15; grp++) {
        float m  = fmaxf(smax[0], smax[1]);
        float sc = __fdividef(1.0f, m);
        L += __logf(m);
        #pragma unroll
        for (int q = 0; q < 8; q++) {
            STEP(pe, q & 3, q & 1, (q == 0) ? sc : 1.0f, q == 7);
            pe += TT;
        }
    }
    {
        float m  = fmaxf(smax[0], smax[1]);
        float sc = __fdividef(1.0f, m);
        L += __logf(m);
        #pragma unroll
        for (int q = 0; q < 7; q++) {          // t = 121..127; refill only t<124
            STEP((q < 3) ? pe : (const float*)0, q & 3, q & 1, (q == 0) ? sc : 1.0f, false);
            pe += TT;
        }
    }

    // ---- epilogue: logZ = log(sum_j u_j * exp(end_j)) + L ----
    float ws = r * eEnd;
    if (lane == 0) ws += rx * eEndX;
    #pragma unroll
    for (int o = 16; o; o >>= 1) ws += __shfl_xor_sync(~0u, ws, o);
    if (lane == 0) swsum[w] = ws;
    __syncthreads();

    if (tid == 0) {
        float logZ = __logf(swsum[0] + swsum[1]) + L;
        __stcg(&g_partial[seq], logZ - (sgold[0] + sgold[1]));
        __threadfence();
        unsigned cc = atomicAdd(&g_count, 1u);
        sflag = (cc == NSEQ - 1) ? 1 : 0;
    }
    __syncthreads();

    // ---- fused final reduction in the last block ----
    if (sflag) {
        float v = 0.f;
        #pragma unroll
        for (int p = 0; p < 4; p++) v += __ldcg(&g_partial[tid + 64*p]);
        #pragma unroll
        for (int o = 16; o; o >>= 1) v += __shfl_xor_sync(~0u, v, o);
        if (lane == 0) sred[w] = v;
        __syncthreads();
        if (tid == 0) {
            out[0] = (sred[0] + sred[1]) * (1.0f / (float)NSEQ);
            g_count = 0;                       // reset for next graph replay
        }
    }
}

extern "C" void kernel_launch(void* const* d_in, const int* in_sizes, int n_in,
                              void* d_out, int out_size) {
    const float* score      = (const float*)d_in[0];
    const float* trans      = (const float*)d_in[1];
    const float* startT     = (const float*)d_in[2];
    const float* endT       = (const float*)d_in[3];
    const int*   v_label    = (const int*)d_in[4];
    const int*   role_label = (const int*)d_in[5];
    float* out = (float*)d_out;

    crf_kernel<<<NSEQ, 64>>>(score, trans, startT, endT, v_label, role_label, out);
}